// round 13
// baseline (speedup 1.0000x reference)
#include <cuda_runtime.h>
#include <cuda_fp16.h>

// Problem constants
#define S      2785
#define S32    (S * 32)
#define G      689
#define NCH    256            // batch chunks of 32
#define CAP    192            // max nnz per column
#define CAPP   (CAP / 2)      // entry pairs
#define NLAY   7
#define RSPLIT 8
#define NW     88             // bitmap words per column
#define WPC    11
#define NB     349            // column blocks of 8
#define NBP8   (NB * 8)
#define NFULL  148            // full-chunk CTAs (chunks 0..147)
#define NQRT   432            // quarter-chunk CTAs (chunks 148..255, x4)
#define NGRID  (NFULL + NQRT) // 580
#define SSTRIDE 80            // smem bytes per slot (32 halfs + 16B pad)

// ---------------- device global scratch ---------------------------------------
__device__ __half    g_actA[(size_t)NCH * S32];
__device__ __half    g_actB[(size_t)NCH * S32];
__device__ float     g_Y[(size_t)NCH * S32];
__device__ int4      g_be2[(size_t)NLAY * NB * CAPP * 8];
__device__ float2    g_part[(size_t)S * NCH];
__device__ float4    g_stat[S];                  // {mean, gamma*rstd, beta, d}
__device__ unsigned  g_bits[(size_t)NLAY * NW * S];
__device__ int       g_cnt[NLAY * S];
__device__ int       g_off8[NLAY * RSPLIT * S];
__device__ int       g_perm[NLAY * NBP8];
__device__ int       g_scnt[NLAY * NBP8];
__device__ int       g_blkmax[NLAY * NB];

__device__ __forceinline__ __half* getact(int s) { return s == 0 ? g_actA : g_actB; }

// packed f32x2 helpers (Blackwell FFMA2 path)
__device__ __forceinline__ unsigned long long h2_up(unsigned h2) {
    float2 f = __half22float2(*(__half2*)&h2);
    unsigned long long r;
    asm("mov.b64 %0, {%1, %2};" : "=l"(r) : "f"(f.x), "f"(f.y));
    return r;
}
__device__ __forceinline__ unsigned long long f_dup(float w) {
    unsigned long long r;
    asm("mov.b64 %0, {%1, %1};" : "=l"(r) : "f"(w));
    return r;
}
__device__ __forceinline__ void ffma2(unsigned long long& acc,
                                      unsigned long long a, unsigned long long b) {
    asm("fma.rn.f32x2 %0, %1, %2, %0;" : "+l"(acc) : "l"(a), "l"(b));
}
__device__ __forceinline__ float2 unpk(unsigned long long v) {
    float2 f;
    asm("mov.b64 {%0, %1}, %2;" : "=f"(f.x), "=f"(f.y) : "l"(v));
    return f;
}

// ---------------- build phase A: occupancy bitmaps ----------------------------
__global__ void bits_kernel(const float* __restrict__ lm0, const float* __restrict__ lm) {
    int l = blockIdx.y;
    int w = blockIdx.z;
    int j = blockIdx.x * 128 + threadIdx.x;
    if (j >= S) return;
    int rows = (l == 0) ? G : S;
    unsigned m = 0;
    int i0 = w * 32;
    if (i0 < rows) {
        const float* M = (l == 0) ? lm0 : lm + (size_t)(l - 1) * S * S;
        const float* Mr = M + (size_t)i0 * S + j;
        if (i0 + 32 <= rows) {
            #pragma unroll
            for (int k = 0; k < 32; k++)
                m |= (Mr[(size_t)k * S] != 0.f ? 1u : 0u) << k;
        } else {
            int n = rows - i0;
            for (int k = 0; k < n; k++)
                m |= (Mr[(size_t)k * S] != 0.f ? 1u : 0u) << k;
        }
    }
    g_bits[((size_t)l * NW + w) * S + j] = m;
}

// ---------------- build phase B: per-chunk popc prefix ------------------------
__global__ void prefix_kernel() {
    int l = blockIdx.y;
    int j = blockIdx.x * 128 + threadIdx.x;
    if (j >= S) return;
    int off = 0;
    #pragma unroll
    for (int r = 0; r < RSPLIT; r++) {
        int c = 0;
        #pragma unroll
        for (int w = r * WPC; w < (r + 1) * WPC; w++)
            c += __popc(g_bits[((size_t)l * NW + w) * S + j]);
        g_off8[(l * RSPLIT + r) * S + j] = off;
        off += c;
    }
    g_cnt[l * S + j] = min(off, CAP);
}

// ---------------- build phase C: deterministic rank-sort ----------------------
#define S4 ((S + 3) / 4)
__global__ __launch_bounds__(1024)
void sort_kernel() {
    int l = blockIdx.y;
    __shared__ int4 scnt4[S4];
    int* scnt = (int*)scnt4;
    for (int j = threadIdx.x; j < S4 * 4; j += 1024)
        scnt[j] = (j < S) ? g_cnt[l * S + j] : -1;
    __syncthreads();

    int j = blockIdx.x * 1024 + threadIdx.x;
    if (j < S) {
        int c = scnt[j];
        int pos = 0;
        for (int q = 0; q < S4; q++) {
            int4 v = scnt4[q];
            int b0 = 4 * q;
            pos += (v.x > c) || (v.x == c && b0 + 0 < j);
            pos += (v.y > c) || (v.y == c && b0 + 1 < j);
            pos += (v.z > c) || (v.z == c && b0 + 2 < j);
            pos += (v.w > c) || (v.w == c && b0 + 3 < j);
        }
        g_perm[l * NBP8 + pos] = j;
        g_scnt[l * NBP8 + pos] = c;
        if ((pos & 7) == 0) g_blkmax[l * NB + (pos >> 3)] = c;
    }
    if (blockIdx.x == 0)
        for (int p = S + threadIdx.x; p < NBP8; p += 1024) {
            g_perm[l * NBP8 + p] = -1;
            g_scnt[l * NBP8 + p] = 0;
        }
}

// ---------------- build phase D: fill entries from bitmaps + zero-pad --------
__global__ void fill_kernel(const float* __restrict__ W0, const float* __restrict__ Wl) {
    int l = blockIdx.y, r = blockIdx.z;
    int p = blockIdx.x * 128 + threadIdx.x;
    if (p >= NBP8) return;
    int j = g_perm[l * NBP8 + p];
    int b = p >> 3, g = p & 7;
    int2* e2 = (int2*)g_be2;
    size_t bi = (size_t)(l * NB + b) * CAPP;
    int km = g_blkmax[l * NB + b];
    int kmpad = ((km + 1) >> 1) << 1;

    if (j < 0) {
        if (r == RSPLIT - 1)
            for (int k = 0; k < kmpad; k++)
                e2[((bi + (k >> 1)) * 8 + g) * 2 + (k & 1)] = make_int2(0, 0);
        return;
    }
    const float* Wm = (l == 0) ? W0 : Wl + (size_t)(l - 1) * S * S;
    int o = g_off8[(l * RSPLIT + r) * S + j];
    for (int w = r * WPC; w < (r + 1) * WPC; w++) {
        unsigned m = g_bits[((size_t)l * NW + w) * S + j];
        int ibase = w * 32;
        while (m) {
            int k = __ffs(m) - 1;
            m &= m - 1;
            int i = ibase + k;
            if (o < CAP) {
                float wv = Wm[(size_t)i * S + j];
                e2[((bi + (o >> 1)) * 8 + g) * 2 + (o & 1)] =
                    make_int2(i * SSTRIDE, __float_as_int(wv));
            }
            o++;
        }
    }
    if (r == RSPLIT - 1) {
        int start = g_scnt[l * NBP8 + p];
        for (int k = start; k < kmpad; k++)
            e2[((bi + (k >> 1)) * 8 + g) * 2 + (k & 1)] = make_int2(0, 0);
    }
}

// ---------------- coalesced transpose x [B,G] -> [NCH][G][32] fp16 -----------
#define XT_TI 128
__global__ __launch_bounds__(256)
void xt_kernel(const float* __restrict__ x) {
    __shared__ float tile[32][XT_TI + 1];
    int c  = blockIdx.y;
    int i0 = blockIdx.x * XT_TI;
    int t  = threadIdx.x;
    int col = t & 127;
    #pragma unroll
    for (int rr = 0; rr < 16; rr++) {
        int row = rr * 2 + (t >> 7);
        int i = i0 + col;
        tile[row][col] = (i < G) ? x[(size_t)(c * 32 + row) * G + i] : 0.f;
    }
    __syncthreads();
    int lane = t & 31;
    int ii0 = t >> 5;
    #pragma unroll
    for (int bq = 0; bq < 16; bq++) {
        int ii = ii0 + bq * 8;
        int i = i0 + ii;
        if (i < G)
            g_actA[(size_t)c * (G * 32) + (size_t)i * 32 + lane] =
                __float2half_rn(tile[lane][ii]);
    }
}

// ---------------- fused SpMM: BN/tanh/skip tile-load + sparse gather + stats --
// 32-wide chunks; gather math on packed f32x2 FFMA2 (bit-identical to 2x fmaf).
__global__ __launch_bounds__(1024, 1)
void spmm_kernel(int mode, int wsel, int ssel, int layer, int n_slots) {
    extern __shared__ char xs[];

    int w     = threadIdx.x >> 5;
    int lane  = threadIdx.x & 31;
    int g     = lane >> 2;
    int lane4 = lane & 3;
    const char* xsb = xs + lane4 * 16;

    int bid = blockIdx.x;
    int c, b0, bstep, writeact;
    if (bid < NFULL) { c = bid; b0 = w; bstep = 32; writeact = 1; }
    else {
        int t = bid - NFULL;
        c = NFULL + (t >> 2);
        int qi = t & 3;
        b0 = qi + (w << 2);
        bstep = 128;
        writeact = (qi == 0);
    }

    if (mode == 0) {
        const uint4* src = (const uint4*)(g_actA + (size_t)c * n_slots * 32);
        int nq = n_slots * 4;
        for (int t = threadIdx.x; t < nq; t += 1024) {
            int slot = t >> 2, q = t & 3;
            *(uint4*)(xs + slot * SSTRIDE + q * 16) = src[t];
        }
    } else {
        const float* Yc = g_Y + (size_t)c * S32;
        const __half* skp = getact(ssel) + (size_t)c * S32;
        __half* actw = getact(wsel) + (size_t)c * S32;
        for (int q = threadIdx.x; q < S * 8; q += 1024) {
            int slot = q >> 3, oct = q & 7;
            float4 st = g_stat[slot];                 // {m, gs, bt, d}
            float4 y  = *(const float4*)(Yc + slot * 32 + oct * 4);
            uint2 sk  = *(const uint2*)(skp + slot * 32 + oct * 4);
            float2 s0 = __half22float2(*(__half2*)&sk.x);
            float2 s1 = __half22float2(*(__half2*)&sk.y);
            float a0 = tanhf((y.x - st.x) * st.y + st.z) + s0.x * st.w;
            float a1 = tanhf((y.y - st.x) * st.y + st.z) + s0.y * st.w;
            float a2 = tanhf((y.z - st.x) * st.y + st.z) + s1.x * st.w;
            float a3 = tanhf((y.w - st.x) * st.y + st.z) + s1.y * st.w;
            __half2 h0 = __floats2half2_rn(a0, a1);
            __half2 h1 = __floats2half2_rn(a2, a3);
            uint2 pk;
            *(__half2*)&pk.x = h0;
            *(__half2*)&pk.y = h1;
            *(uint2*)(xs + slot * SSTRIDE + oct * 8) = pk;
            if (writeact) *(uint2*)(actw + slot * 32 + oct * 4) = pk;
        }
    }
    __syncthreads();

    float* yb = g_Y + (size_t)c * S32;
    for (int b = b0; b < NB; b += bstep) {
        int pp = b * 8 + g;
        int j  = g_perm[layer * NBP8 + pp];
        int km = g_blkmax[layer * NB + b];
        int kmp = (km + 1) >> 1;
        const int4* ep4 = g_be2 + (size_t)(layer * NB + b) * CAPP * 8 + g;
        unsigned long long acc0 = 0, acc1 = 0, acc2 = 0, acc3 = 0; // f32x2 {0,0}
        if (kmp > 0) {
            int4 e = ep4[0];
            for (int kp = 0; kp < kmp; kp++) {
                int4 en;
                if (kp + 1 < kmp) en = ep4[(size_t)(kp + 1) * 8];
                uint4 r0 = *(const uint4*)(xsb + e.x);
                uint4 r1 = *(const uint4*)(xsb + e.z);
                unsigned long long w0p = f_dup(__int_as_float(e.y));
                unsigned long long w1p = f_dup(__int_as_float(e.w));
                ffma2(acc0, h2_up(r0.x), w0p);
                ffma2(acc1, h2_up(r0.y), w0p);
                ffma2(acc2, h2_up(r0.z), w0p);
                ffma2(acc3, h2_up(r0.w), w0p);
                ffma2(acc0, h2_up(r1.x), w1p);
                ffma2(acc1, h2_up(r1.y), w1p);
                ffma2(acc2, h2_up(r1.z), w1p);
                ffma2(acc3, h2_up(r1.w), w1p);
                e = en;
            }
        }
        float2 f0 = unpk(acc0), f1 = unpk(acc1), f2 = unpk(acc2), f3 = unpk(acc3);
        // BN partials: shuffles MUST run convergent (pad lanes j==-1 included).
        float s  = f0.x + f0.y + f1.x + f1.y + f2.x + f2.y + f3.x + f3.y;
        float ss = f0.x * f0.x + f0.y * f0.y + f1.x * f1.x + f1.y * f1.y
                 + f2.x * f2.x + f2.y * f2.y + f3.x * f3.x + f3.y * f3.y;
        s  += __shfl_xor_sync(0xffffffffu, s, 1);
        ss += __shfl_xor_sync(0xffffffffu, ss, 1);
        s  += __shfl_xor_sync(0xffffffffu, s, 2);
        ss += __shfl_xor_sync(0xffffffffu, ss, 2);
        if (j >= 0) {
            float4* dst = (float4*)(yb + (size_t)j * 32 + lane4 * 8);
            dst[0] = make_float4(f0.x, f0.y, f1.x, f1.y);
            dst[1] = make_float4(f2.x, f2.y, f3.x, f3.y);
            if (lane4 == 0)
                g_part[(size_t)j * NCH + c] = make_float2(s, ss);
        }
    }
}

// ---------------- stats: fold partials + gamma/beta/diag into float4 ---------
__global__ __launch_bounds__(256)
void stats_kernel(const float* __restrict__ gamma, const float* __restrict__ beta,
                  const float* __restrict__ dvec) {
    int j = blockIdx.x * 8 + (threadIdx.x >> 5);
    if (j >= S) return;
    int ln = threadIdx.x & 31;
    const float2* pt = g_part + (size_t)j * NCH;
    float s = 0.f, ss = 0.f;
    #pragma unroll
    for (int i = 0; i < 8; i++) {
        float2 v = pt[ln + 32 * i];
        s += v.x; ss += v.y;
    }
    #pragma unroll
    for (int o = 16; o; o >>= 1) {
        s  += __shfl_xor_sync(0xffffffffu, s,  o);
        ss += __shfl_xor_sync(0xffffffffu, ss, o);
    }
    if (ln == 0) {
        float m   = s * (1.f / 8192.f);
        float var = ss * (1.f / 8192.f) - m * m;
        float rstd = rsqrtf(var + 1e-5f);
        g_stat[j] = make_float4(m, gamma[j] * rstd, beta[j],
                                dvec ? dvec[j] : 0.f);
    }
}

// ---------------- output head: applies layer-6 BN/tanh/skip inline -----------
__global__ __launch_bounds__(512)
void out_kernel(int ssel, const float* __restrict__ fasm,
                const float* __restrict__ wout, const float* __restrict__ bout,
                float* __restrict__ out) {
    __shared__ float fw[S];
    for (int i = threadIdx.x; i < S; i += blockDim.x) fw[i] = fasm[i] * wout[i];
    __syncthreads();
    int b = blockIdx.x * blockDim.x + threadIdx.x;
    int c = b >> 5, lane = b & 31;
    const float*  Yb = g_Y + (size_t)c * S32 + lane;
    const __half* sb = getact(ssel) + (size_t)c * S32 + lane;
    float s = *bout;
    for (int jj = 0; jj < S; jj++) {
        float f = fw[jj];
        if (f != 0.f) {
            float4 st = g_stat[jj];
            float y  = Yb[(size_t)jj * 32];
            float a5 = __half2float(sb[(size_t)jj * 32]);
            float a6 = tanhf((y - st.x) * st.y + st.z) + a5 * st.w;
            s += a6 * f;
        }
    }
    out[b] = s;
}

// ---------------- launch ------------------------------------------------------
extern "C" void kernel_launch(void* const* d_in, const int* in_sizes, int n_in,
                              void* d_out, int out_size) {
    const float* x     = (const float*)d_in[0];
    const float* lm0   = (const float*)d_in[1];
    const float* lm    = (const float*)d_in[2];
    const float* flm   = (const float*)d_in[3];
    const float* fasm  = (const float*)d_in[4];
    const float* W0    = (const float*)d_in[5];
    const float* W     = (const float*)d_in[7];
    const float* gamma = (const float*)d_in[9];
    const float* beta  = (const float*)d_in[10];
    const float* wout  = (const float*)d_in[11];
    const float* bout  = (const float*)d_in[12];
    float* out = (float*)d_out;
    // note: biases b0/b (d_in[6], d_in[8]) cancel exactly through training-mode BN

    cudaFuncSetAttribute(spmm_kernel, cudaFuncAttributeMaxDynamicSharedMemorySize,
                         S * SSTRIDE);

    // 1) build sparse structure
    bits_kernel<<<dim3((S + 127) / 128, NLAY, NW), 128>>>(lm0, lm);
    prefix_kernel<<<dim3((S + 127) / 128, NLAY), 128>>>();
    sort_kernel<<<dim3((S + 1023) / 1024, NLAY), 1024>>>();
    fill_kernel<<<dim3((NBP8 + 127) / 128, NLAY, RSPLIT), 128>>>(W0, W);

    // 2) transpose x -> actA (fp16, 32-wide chunks)
    xt_kernel<<<dim3((G + XT_TI - 1) / XT_TI, NCH), 256>>>(x);

    // 3) layer 0
    spmm_kernel<<<NGRID, 1024, G * SSTRIDE>>>(0, 0, 0, 0, G);
    stats_kernel<<<(S + 7) / 8, 256>>>(gamma, beta, nullptr);

    // 4) layers 1..6
    for (int l = 1; l <= 6; l++) {
        int wsel = (l & 1) ? 1 : 0;
        int ssel = 1 - wsel;
        spmm_kernel<<<NGRID, 1024, S * SSTRIDE>>>(1, wsel, ssel, l, S);
        stats_kernel<<<(S + 7) / 8, 256>>>(gamma + (size_t)l * S,
                                           beta + (size_t)l * S,
                                           flm + (size_t)(l - 1) * S);
    }

    // 5) output head
    out_kernel<<<16, 512>>>(0, fasm, wout, bout, out);
}

// round 14
// speedup vs baseline: 1.0066x; 1.0066x over previous
#include <cuda_runtime.h>
#include <cuda_fp16.h>

// Problem constants
#define S      2785
#define S32    (S * 32)
#define G      689
#define NCH    256            // batch chunks of 32
#define CAP    192            // max nnz per column
#define CAPP   (CAP / 2)      // entry pairs
#define NLAY   7
#define RSPLIT 8
#define NW     88             // bitmap words per column
#define WPC    11
#define NB     349            // column blocks of 8
#define NBP8   (NB * 8)
#define NFULL  148            // full-chunk CTAs (chunks 0..147)
#define NQRT   432            // quarter-chunk CTAs (chunks 148..255, x4)
#define NGRID  (NFULL + NQRT) // 580
#define SSTRIDE 80            // smem bytes per slot (32 halfs + 16B pad)

// ---------------- device global scratch ---------------------------------------
__device__ __half    g_actA[(size_t)NCH * S32];
__device__ __half    g_actB[(size_t)NCH * S32];
__device__ float     g_Y[(size_t)NCH * S32];
__device__ int4      g_be2[(size_t)NLAY * NB * CAPP * 8];
__device__ float2    g_part[(size_t)S * NCH];
__device__ float4    g_stat[S];                  // {mean, gamma*rstd, beta, d}
__device__ unsigned  g_bits[(size_t)NLAY * NW * S];
__device__ int       g_cnt[NLAY * S];
__device__ int       g_off8[NLAY * RSPLIT * S];
__device__ int       g_perm[NLAY * NBP8];
__device__ int       g_scnt[NLAY * NBP8];
__device__ int       g_blkmax[NLAY * NB];

__device__ __forceinline__ __half* getact(int s) { return s == 0 ? g_actA : g_actB; }

// packed f32x2 helpers (Blackwell FFMA2 path)
__device__ __forceinline__ unsigned long long h2_up(unsigned h2) {
    float2 f = __half22float2(*(__half2*)&h2);
    unsigned long long r;
    asm("mov.b64 %0, {%1, %2};" : "=l"(r) : "f"(f.x), "f"(f.y));
    return r;
}
__device__ __forceinline__ unsigned long long f_dup(float w) {
    unsigned long long r;
    asm("mov.b64 %0, {%1, %1};" : "=l"(r) : "f"(w));
    return r;
}
__device__ __forceinline__ void ffma2(unsigned long long& acc,
                                      unsigned long long a, unsigned long long b) {
    asm("fma.rn.f32x2 %0, %1, %2, %0;" : "+l"(acc) : "l"(a), "l"(b));
}
__device__ __forceinline__ float2 unpk(unsigned long long v) {
    float2 f;
    asm("mov.b64 {%0, %1}, %2;" : "=f"(f.x), "=f"(f.y) : "l"(v));
    return f;
}

// ---------------- build phase A: occupancy bitmaps ----------------------------
__global__ void bits_kernel(const float* __restrict__ lm0, const float* __restrict__ lm) {
    int l = blockIdx.y;
    int w = blockIdx.z;
    int j = blockIdx.x * 128 + threadIdx.x;
    if (j >= S) return;
    int rows = (l == 0) ? G : S;
    unsigned m = 0;
    int i0 = w * 32;
    if (i0 < rows) {
        const float* M = (l == 0) ? lm0 : lm + (size_t)(l - 1) * S * S;
        const float* Mr = M + (size_t)i0 * S + j;
        if (i0 + 32 <= rows) {
            #pragma unroll
            for (int k = 0; k < 32; k++)
                m |= (Mr[(size_t)k * S] != 0.f ? 1u : 0u) << k;
        } else {
            int n = rows - i0;
            for (int k = 0; k < n; k++)
                m |= (Mr[(size_t)k * S] != 0.f ? 1u : 0u) << k;
        }
    }
    g_bits[((size_t)l * NW + w) * S + j] = m;
}

// ---------------- build phase B: per-chunk popc prefix ------------------------
__global__ void prefix_kernel() {
    int l = blockIdx.y;
    int j = blockIdx.x * 128 + threadIdx.x;
    if (j >= S) return;
    int off = 0;
    #pragma unroll
    for (int r = 0; r < RSPLIT; r++) {
        int c = 0;
        #pragma unroll
        for (int w = r * WPC; w < (r + 1) * WPC; w++)
            c += __popc(g_bits[((size_t)l * NW + w) * S + j]);
        g_off8[(l * RSPLIT + r) * S + j] = off;
        off += c;
    }
    g_cnt[l * S + j] = min(off, CAP);
}

// ---------------- build phase C: deterministic rank-sort ----------------------
#define S4 ((S + 3) / 4)
__global__ __launch_bounds__(1024)
void sort_kernel() {
    int l = blockIdx.y;
    __shared__ int4 scnt4[S4];
    int* scnt = (int*)scnt4;
    for (int j = threadIdx.x; j < S4 * 4; j += 1024)
        scnt[j] = (j < S) ? g_cnt[l * S + j] : -1;
    __syncthreads();

    int j = blockIdx.x * 1024 + threadIdx.x;
    if (j < S) {
        int c = scnt[j];
        int pos = 0;
        for (int q = 0; q < S4; q++) {
            int4 v = scnt4[q];
            int b0 = 4 * q;
            pos += (v.x > c) || (v.x == c && b0 + 0 < j);
            pos += (v.y > c) || (v.y == c && b0 + 1 < j);
            pos += (v.z > c) || (v.z == c && b0 + 2 < j);
            pos += (v.w > c) || (v.w == c && b0 + 3 < j);
        }
        g_perm[l * NBP8 + pos] = j;
        g_scnt[l * NBP8 + pos] = c;
        if ((pos & 7) == 0) g_blkmax[l * NB + (pos >> 3)] = c;
    }
    if (blockIdx.x == 0)
        for (int p = S + threadIdx.x; p < NBP8; p += 1024) {
            g_perm[l * NBP8 + p] = -1;
            g_scnt[l * NBP8 + p] = 0;
        }
}

// ---------------- build phase D: fill entries from bitmaps + zero-pad --------
__global__ void fill_kernel(const float* __restrict__ W0, const float* __restrict__ Wl) {
    int l = blockIdx.y, r = blockIdx.z;
    int p = blockIdx.x * 128 + threadIdx.x;
    if (p >= NBP8) return;
    int j = g_perm[l * NBP8 + p];
    int b = p >> 3, g = p & 7;
    int2* e2 = (int2*)g_be2;
    size_t bi = (size_t)(l * NB + b) * CAPP;
    int km = g_blkmax[l * NB + b];
    int kmpad = ((km + 1) >> 1) << 1;

    if (j < 0) {
        if (r == RSPLIT - 1)
            for (int k = 0; k < kmpad; k++)
                e2[((bi + (k >> 1)) * 8 + g) * 2 + (k & 1)] = make_int2(0, 0);
        return;
    }
    const float* Wm = (l == 0) ? W0 : Wl + (size_t)(l - 1) * S * S;
    int o = g_off8[(l * RSPLIT + r) * S + j];
    for (int w = r * WPC; w < (r + 1) * WPC; w++) {
        unsigned m = g_bits[((size_t)l * NW + w) * S + j];
        int ibase = w * 32;
        while (m) {
            int k = __ffs(m) - 1;
            m &= m - 1;
            int i = ibase + k;
            if (o < CAP) {
                float wv = Wm[(size_t)i * S + j];
                e2[((bi + (o >> 1)) * 8 + g) * 2 + (o & 1)] =
                    make_int2(i * SSTRIDE, __float_as_int(wv));
            }
            o++;
        }
    }
    if (r == RSPLIT - 1) {
        int start = g_scnt[l * NBP8 + p];
        for (int k = start; k < kmpad; k++)
            e2[((bi + (k >> 1)) * 8 + g) * 2 + (k & 1)] = make_int2(0, 0);
    }
}

// ---------------- coalesced transpose x [B,G] -> [NCH][G][32] fp16 -----------
#define XT_TI 128
__global__ __launch_bounds__(256)
void xt_kernel(const float* __restrict__ x) {
    __shared__ float tile[32][XT_TI + 1];
    int c  = blockIdx.y;
    int i0 = blockIdx.x * XT_TI;
    int t  = threadIdx.x;
    int col = t & 127;
    #pragma unroll
    for (int rr = 0; rr < 16; rr++) {
        int row = rr * 2 + (t >> 7);
        int i = i0 + col;
        tile[row][col] = (i < G) ? x[(size_t)(c * 32 + row) * G + i] : 0.f;
    }
    __syncthreads();
    int lane = t & 31;
    int ii0 = t >> 5;
    #pragma unroll
    for (int bq = 0; bq < 16; bq++) {
        int ii = ii0 + bq * 8;
        int i = i0 + ii;
        if (i < G)
            g_actA[(size_t)c * (G * 32) + (size_t)i * 32 + lane] =
                __float2half_rn(tile[lane][ii]);
    }
}

// ---------------- fused SpMM: BN/tanh/skip tile-load + sparse gather + stats --
// 32-wide chunks; gather math on packed f32x2 FFMA2 (bit-identical to 2x fmaf).
__global__ __launch_bounds__(1024, 1)
void spmm_kernel(int mode, int wsel, int ssel, int layer, int n_slots) {
    extern __shared__ char xs[];

    int w     = threadIdx.x >> 5;
    int lane  = threadIdx.x & 31;
    int g     = lane >> 2;
    int lane4 = lane & 3;
    const char* xsb = xs + lane4 * 16;

    int bid = blockIdx.x;
    int c, b0, bstep, writeact;
    if (bid < NFULL) { c = bid; b0 = w; bstep = 32; writeact = 1; }
    else {
        int t = bid - NFULL;
        c = NFULL + (t >> 2);
        int qi = t & 3;
        b0 = qi + (w << 2);
        bstep = 128;
        writeact = (qi == 0);
    }

    if (mode == 0) {
        const uint4* src = (const uint4*)(g_actA + (size_t)c * n_slots * 32);
        int nq = n_slots * 4;
        for (int t = threadIdx.x; t < nq; t += 1024) {
            int slot = t >> 2, q = t & 3;
            *(uint4*)(xs + slot * SSTRIDE + q * 16) = src[t];
        }
    } else {
        const float* Yc = g_Y + (size_t)c * S32;
        const __half* skp = getact(ssel) + (size_t)c * S32;
        __half* actw = getact(wsel) + (size_t)c * S32;
        for (int q = threadIdx.x; q < S * 8; q += 1024) {
            int slot = q >> 3, oct = q & 7;
            float4 st = g_stat[slot];                 // {m, gs, bt, d}
            float4 y  = *(const float4*)(Yc + slot * 32 + oct * 4);
            uint2 sk  = *(const uint2*)(skp + slot * 32 + oct * 4);
            float2 s0 = __half22float2(*(__half2*)&sk.x);
            float2 s1 = __half22float2(*(__half2*)&sk.y);
            float a0 = tanhf((y.x - st.x) * st.y + st.z) + s0.x * st.w;
            float a1 = tanhf((y.y - st.x) * st.y + st.z) + s0.y * st.w;
            float a2 = tanhf((y.z - st.x) * st.y + st.z) + s1.x * st.w;
            float a3 = tanhf((y.w - st.x) * st.y + st.z) + s1.y * st.w;
            __half2 h0 = __floats2half2_rn(a0, a1);
            __half2 h1 = __floats2half2_rn(a2, a3);
            uint2 pk;
            *(__half2*)&pk.x = h0;
            *(__half2*)&pk.y = h1;
            *(uint2*)(xs + slot * SSTRIDE + oct * 8) = pk;
            if (writeact) *(uint2*)(actw + slot * 32 + oct * 4) = pk;
        }
    }
    __syncthreads();

    float* yb = g_Y + (size_t)c * S32;
    for (int b = b0; b < NB; b += bstep) {
        int pp = b * 8 + g;
        int j  = g_perm[layer * NBP8 + pp];
        int km = g_blkmax[layer * NB + b];
        int kmp = (km + 1) >> 1;
        const int4* ep4 = g_be2 + (size_t)(layer * NB + b) * CAPP * 8 + g;
        unsigned long long acc0 = 0, acc1 = 0, acc2 = 0, acc3 = 0; // f32x2 {0,0}
        if (kmp > 0) {
            int4 e = ep4[0];
            for (int kp = 0; kp < kmp; kp++) {
                int4 en;
                if (kp + 1 < kmp) en = ep4[(size_t)(kp + 1) * 8];
                uint4 r0 = *(const uint4*)(xsb + e.x);
                uint4 r1 = *(const uint4*)(xsb + e.z);
                unsigned long long w0p = f_dup(__int_as_float(e.y));
                unsigned long long w1p = f_dup(__int_as_float(e.w));
                ffma2(acc0, h2_up(r0.x), w0p);
                ffma2(acc1, h2_up(r0.y), w0p);
                ffma2(acc2, h2_up(r0.z), w0p);
                ffma2(acc3, h2_up(r0.w), w0p);
                ffma2(acc0, h2_up(r1.x), w1p);
                ffma2(acc1, h2_up(r1.y), w1p);
                ffma2(acc2, h2_up(r1.z), w1p);
                ffma2(acc3, h2_up(r1.w), w1p);
                e = en;
            }
        }
        float2 f0 = unpk(acc0), f1 = unpk(acc1), f2 = unpk(acc2), f3 = unpk(acc3);
        // BN partials: shuffles MUST run convergent (pad lanes j==-1 included).
        float s  = f0.x + f0.y + f1.x + f1.y + f2.x + f2.y + f3.x + f3.y;
        float ss = f0.x * f0.x + f0.y * f0.y + f1.x * f1.x + f1.y * f1.y
                 + f2.x * f2.x + f2.y * f2.y + f3.x * f3.x + f3.y * f3.y;
        s  += __shfl_xor_sync(0xffffffffu, s, 1);
        ss += __shfl_xor_sync(0xffffffffu, ss, 1);
        s  += __shfl_xor_sync(0xffffffffu, s, 2);
        ss += __shfl_xor_sync(0xffffffffu, ss, 2);
        if (j >= 0) {
            float4* dst = (float4*)(yb + (size_t)j * 32 + lane4 * 8);
            dst[0] = make_float4(f0.x, f0.y, f1.x, f1.y);
            dst[1] = make_float4(f2.x, f2.y, f3.x, f3.y);
            if (lane4 == 0)
                g_part[(size_t)j * NCH + c] = make_float2(s, ss);
        }
    }
}

// ---------------- stats: fold partials + gamma/beta/diag into float4 ---------
__global__ __launch_bounds__(256)
void stats_kernel(const float* __restrict__ gamma, const float* __restrict__ beta,
                  const float* __restrict__ dvec) {
    int j = blockIdx.x * 8 + (threadIdx.x >> 5);
    if (j >= S) return;
    int ln = threadIdx.x & 31;
    const float2* pt = g_part + (size_t)j * NCH;
    float s = 0.f, ss = 0.f;
    #pragma unroll
    for (int i = 0; i < 8; i++) {
        float2 v = pt[ln + 32 * i];
        s += v.x; ss += v.y;
    }
    #pragma unroll
    for (int o = 16; o; o >>= 1) {
        s  += __shfl_xor_sync(0xffffffffu, s,  o);
        ss += __shfl_xor_sync(0xffffffffu, ss, o);
    }
    if (ln == 0) {
        float m   = s * (1.f / 8192.f);
        float var = ss * (1.f / 8192.f) - m * m;
        float rstd = rsqrtf(var + 1e-5f);
        g_stat[j] = make_float4(m, gamma[j] * rstd, beta[j],
                                dvec ? dvec[j] : 0.f);
    }
}

// ---------------- output head: applies layer-6 BN/tanh/skip inline -----------
__global__ __launch_bounds__(512)
void out_kernel(int ssel, const float* __restrict__ fasm,
                const float* __restrict__ wout, const float* __restrict__ bout,
                float* __restrict__ out) {
    __shared__ float fw[S];
    for (int i = threadIdx.x; i < S; i += blockDim.x) fw[i] = fasm[i] * wout[i];
    __syncthreads();
    int b = blockIdx.x * blockDim.x + threadIdx.x;
    int c = b >> 5, lane = b & 31;
    const float*  Yb = g_Y + (size_t)c * S32 + lane;
    const __half* sb = getact(ssel) + (size_t)c * S32 + lane;
    float s = *bout;
    for (int jj = 0; jj < S; jj++) {
        float f = fw[jj];
        if (f != 0.f) {
            float4 st = g_stat[jj];
            float y  = Yb[(size_t)jj * 32];
            float a5 = __half2float(sb[(size_t)jj * 32]);
            float a6 = tanhf((y - st.x) * st.y + st.z) + a5 * st.w;
            s += a6 * f;
        }
    }
    out[b] = s;
}

// ---------------- launch ------------------------------------------------------
extern "C" void kernel_launch(void* const* d_in, const int* in_sizes, int n_in,
                              void* d_out, int out_size) {
    const float* x     = (const float*)d_in[0];
    const float* lm0   = (const float*)d_in[1];
    const float* lm    = (const float*)d_in[2];
    const float* flm   = (const float*)d_in[3];
    const float* fasm  = (const float*)d_in[4];
    const float* W0    = (const float*)d_in[5];
    const float* W     = (const float*)d_in[7];
    const float* gamma = (const float*)d_in[9];
    const float* beta  = (const float*)d_in[10];
    const float* wout  = (const float*)d_in[11];
    const float* bout  = (const float*)d_in[12];
    float* out = (float*)d_out;
    // note: biases b0/b (d_in[6], d_in[8]) cancel exactly through training-mode BN

    cudaFuncSetAttribute(spmm_kernel, cudaFuncAttributeMaxDynamicSharedMemorySize,
                         S * SSTRIDE);

    // 1) build sparse structure
    bits_kernel<<<dim3((S + 127) / 128, NLAY, NW), 128>>>(lm0, lm);
    prefix_kernel<<<dim3((S + 127) / 128, NLAY), 128>>>();
    sort_kernel<<<dim3((S + 1023) / 1024, NLAY), 1024>>>();
    fill_kernel<<<dim3((NBP8 + 127) / 128, NLAY, RSPLIT), 128>>>(W0, W);

    // 2) transpose x -> actA (fp16, 32-wide chunks)
    xt_kernel<<<dim3((G + XT_TI - 1) / XT_TI, NCH), 256>>>(x);

    // 3) layer 0
    spmm_kernel<<<NGRID, 1024, G * SSTRIDE>>>(0, 0, 0, 0, G);
    stats_kernel<<<(S + 7) / 8, 256>>>(gamma, beta, nullptr);

    // 4) layers 1..6
    for (int l = 1; l <= 6; l++) {
        int wsel = (l & 1) ? 1 : 0;
        int ssel = 1 - wsel;
        spmm_kernel<<<NGRID, 1024, S * SSTRIDE>>>(1, wsel, ssel, l, S);
        stats_kernel<<<(S + 7) / 8, 256>>>(gamma + (size_t)l * S,
                                           beta + (size_t)l * S,
                                           flm + (size_t)(l - 1) * S);
    }

    // 5) output head
    out_kernel<<<16, 512>>>(0, fasm, wout, bout, out);
}

// round 15
// speedup vs baseline: 1.0681x; 1.0611x over previous
#include <cuda_runtime.h>
#include <cuda_fp16.h>

// Problem constants
#define S      2785
#define S32    (S * 32)
#define G      689
#define NCH    256            // batch chunks of 32
#define CAP    192            // max nnz per column
#define CAPP   (CAP / 2)      // entry pairs
#define NLAY   7
#define RSPLIT 8
#define NW     88             // bitmap words per column
#define WPC    11
#define NB     349            // column blocks of 8
#define NBP8   (NB * 8)
#define NFULL  148            // full-chunk CTAs (chunks 0..147)
#define NQRT   432            // quarter-chunk CTAs (chunks 148..255, x4)
#define NGRID  (NFULL + NQRT) // 580
#define SSTRIDE 80            // smem bytes per slot (32 halfs + 16B pad)

// ---------------- device global scratch ---------------------------------------
__device__ __half    g_actA[(size_t)NCH * S32];
__device__ __half    g_actB[(size_t)NCH * S32];
__device__ float     g_Y[(size_t)NCH * S32];
__device__ int4      g_be2[(size_t)NLAY * NB * CAPP * 8];
__device__ float2    g_part[(size_t)S * NCH];
__device__ float4    g_stat[S];                  // {mean, gamma*rstd, beta, d}
__device__ unsigned  g_bits[(size_t)NLAY * NW * S];
__device__ int       g_cnt[NLAY * S];
__device__ int       g_off8[NLAY * RSPLIT * S];
__device__ int       g_perm[NLAY * NBP8];
__device__ int       g_scnt[NLAY * NBP8];
__device__ int       g_blkmax[NLAY * NB];

__device__ __forceinline__ __half* getact(int s) { return s == 0 ? g_actA : g_actB; }

// packed f32x2 helpers (Blackwell FFMA2 path)
__device__ __forceinline__ unsigned long long h2_up(unsigned h2) {
    float2 f = __half22float2(*(__half2*)&h2);
    unsigned long long r;
    asm("mov.b64 %0, {%1, %2};" : "=l"(r) : "f"(f.x), "f"(f.y));
    return r;
}
__device__ __forceinline__ unsigned long long f_dup(float w) {
    unsigned long long r;
    asm("mov.b64 %0, {%1, %1};" : "=l"(r) : "f"(w));
    return r;
}
__device__ __forceinline__ void ffma2(unsigned long long& acc,
                                      unsigned long long a, unsigned long long b) {
    asm("fma.rn.f32x2 %0, %1, %2, %0;" : "+l"(acc) : "l"(a), "l"(b));
}
__device__ __forceinline__ float2 unpk(unsigned long long v) {
    float2 f;
    asm("mov.b64 {%0, %1}, %2;" : "=f"(f.x), "=f"(f.y) : "l"(v));
    return f;
}

// ---------------- build phase A: occupancy bitmaps ----------------------------
__global__ void bits_kernel(const float* __restrict__ lm0, const float* __restrict__ lm) {
    int l = blockIdx.y;
    int w = blockIdx.z;
    int j = blockIdx.x * 128 + threadIdx.x;
    if (j >= S) return;
    int rows = (l == 0) ? G : S;
    unsigned m = 0;
    int i0 = w * 32;
    if (i0 < rows) {
        const float* M = (l == 0) ? lm0 : lm + (size_t)(l - 1) * S * S;
        const float* Mr = M + (size_t)i0 * S + j;
        if (i0 + 32 <= rows) {
            #pragma unroll
            for (int k = 0; k < 32; k++)
                m |= (Mr[(size_t)k * S] != 0.f ? 1u : 0u) << k;
        } else {
            int n = rows - i0;
            for (int k = 0; k < n; k++)
                m |= (Mr[(size_t)k * S] != 0.f ? 1u : 0u) << k;
        }
    }
    g_bits[((size_t)l * NW + w) * S + j] = m;
}

// ---------------- build phase B: per-chunk popc prefix ------------------------
__global__ void prefix_kernel() {
    int l = blockIdx.y;
    int j = blockIdx.x * 128 + threadIdx.x;
    if (j >= S) return;
    int off = 0;
    #pragma unroll
    for (int r = 0; r < RSPLIT; r++) {
        int c = 0;
        #pragma unroll
        for (int w = r * WPC; w < (r + 1) * WPC; w++)
            c += __popc(g_bits[((size_t)l * NW + w) * S + j]);
        g_off8[(l * RSPLIT + r) * S + j] = off;
        off += c;
    }
    g_cnt[l * S + j] = min(off, CAP);
}

// ---------------- build phase C: deterministic rank-sort ----------------------
#define S4 ((S + 3) / 4)
__global__ __launch_bounds__(1024)
void sort_kernel() {
    int l = blockIdx.y;
    __shared__ int4 scnt4[S4];
    int* scnt = (int*)scnt4;
    for (int j = threadIdx.x; j < S4 * 4; j += 1024)
        scnt[j] = (j < S) ? g_cnt[l * S + j] : -1;
    __syncthreads();

    int j = blockIdx.x * 1024 + threadIdx.x;
    if (j < S) {
        int c = scnt[j];
        int pos = 0;
        for (int q = 0; q < S4; q++) {
            int4 v = scnt4[q];
            int b0 = 4 * q;
            pos += (v.x > c) || (v.x == c && b0 + 0 < j);
            pos += (v.y > c) || (v.y == c && b0 + 1 < j);
            pos += (v.z > c) || (v.z == c && b0 + 2 < j);
            pos += (v.w > c) || (v.w == c && b0 + 3 < j);
        }
        g_perm[l * NBP8 + pos] = j;
        g_scnt[l * NBP8 + pos] = c;
        if ((pos & 7) == 0) g_blkmax[l * NB + (pos >> 3)] = c;
    }
    if (blockIdx.x == 0)
        for (int p = S + threadIdx.x; p < NBP8; p += 1024) {
            g_perm[l * NBP8 + p] = -1;
            g_scnt[l * NBP8 + p] = 0;
        }
}

// ---------------- build phase D: fill entries from bitmaps + zero-pad --------
__global__ void fill_kernel(const float* __restrict__ W0, const float* __restrict__ Wl) {
    int l = blockIdx.y, r = blockIdx.z;
    int p = blockIdx.x * 128 + threadIdx.x;
    if (p >= NBP8) return;
    int j = g_perm[l * NBP8 + p];
    int b = p >> 3, g = p & 7;
    int2* e2 = (int2*)g_be2;
    size_t bi = (size_t)(l * NB + b) * CAPP;
    int km = g_blkmax[l * NB + b];
    int kmpad = ((km + 1) >> 1) << 1;

    if (j < 0) {
        if (r == RSPLIT - 1)
            for (int k = 0; k < kmpad; k++)
                e2[((bi + (k >> 1)) * 8 + g) * 2 + (k & 1)] = make_int2(0, 0);
        return;
    }
    const float* Wm = (l == 0) ? W0 : Wl + (size_t)(l - 1) * S * S;
    int o = g_off8[(l * RSPLIT + r) * S + j];
    for (int w = r * WPC; w < (r + 1) * WPC; w++) {
        unsigned m = g_bits[((size_t)l * NW + w) * S + j];
        int ibase = w * 32;
        while (m) {
            int k = __ffs(m) - 1;
            m &= m - 1;
            int i = ibase + k;
            if (o < CAP) {
                float wv = Wm[(size_t)i * S + j];
                e2[((bi + (o >> 1)) * 8 + g) * 2 + (o & 1)] =
                    make_int2(i * SSTRIDE, __float_as_int(wv));
            }
            o++;
        }
    }
    if (r == RSPLIT - 1) {
        int start = g_scnt[l * NBP8 + p];
        for (int k = start; k < kmpad; k++)
            e2[((bi + (k >> 1)) * 8 + g) * 2 + (k & 1)] = make_int2(0, 0);
    }
}

// ---------------- coalesced transpose x [B,G] -> [NCH][G][32] fp16 -----------
#define XT_TI 128
__global__ __launch_bounds__(256)
void xt_kernel(const float* __restrict__ x) {
    __shared__ float tile[32][XT_TI + 1];
    int c  = blockIdx.y;
    int i0 = blockIdx.x * XT_TI;
    int t  = threadIdx.x;
    int col = t & 127;
    #pragma unroll
    for (int rr = 0; rr < 16; rr++) {
        int row = rr * 2 + (t >> 7);
        int i = i0 + col;
        tile[row][col] = (i < G) ? x[(size_t)(c * 32 + row) * G + i] : 0.f;
    }
    __syncthreads();
    int lane = t & 31;
    int ii0 = t >> 5;
    #pragma unroll
    for (int bq = 0; bq < 16; bq++) {
        int ii = ii0 + bq * 8;
        int i = i0 + ii;
        if (i < G)
            g_actA[(size_t)c * (G * 32) + (size_t)i * 32 + lane] =
                __float2half_rn(tile[lane][ii]);
    }
}

// ---------------- t_kernel: act = tanh((Y-m)*gs+bt) + skip*d, ONCE per chunk --
#define TQ ((S * 8 + 511) / 512)   // 44 blocks of 512 per chunk
__global__ __launch_bounds__(512)
void t_kernel(int wsel, int ssel) {
    int c = blockIdx.y;
    int q = blockIdx.x * 512 + threadIdx.x;
    if (q >= S * 8) return;
    int slot = q >> 3, oct = q & 7;
    float4 st = g_stat[slot];                 // {m, gs, bt, d}
    float4 y  = *(const float4*)(g_Y + (size_t)c * S32 + slot * 32 + oct * 4);
    uint2 sk  = *(const uint2*)(getact(ssel) + (size_t)c * S32 + slot * 32 + oct * 4);
    float2 s0 = __half22float2(*(__half2*)&sk.x);
    float2 s1 = __half22float2(*(__half2*)&sk.y);
    float a0 = tanhf((y.x - st.x) * st.y + st.z) + s0.x * st.w;
    float a1 = tanhf((y.y - st.x) * st.y + st.z) + s0.y * st.w;
    float a2 = tanhf((y.z - st.x) * st.y + st.z) + s1.x * st.w;
    float a3 = tanhf((y.w - st.x) * st.y + st.z) + s1.y * st.w;
    __half2 h0 = __floats2half2_rn(a0, a1);
    __half2 h1 = __floats2half2_rn(a2, a3);
    uint2 pk;
    *(__half2*)&pk.x = h0;
    *(__half2*)&pk.y = h1;
    *(uint2*)(getact(wsel) + (size_t)c * S32 + slot * 32 + oct * 4) = pk;
}

// ---------------- SpMM: fp16 tile copy + sparse gather + BN partials ----------
__global__ __launch_bounds__(1024, 1)
void spmm_kernel(int asel, int layer, int n_slots) {
    extern __shared__ char xs[];

    int w     = threadIdx.x >> 5;
    int lane  = threadIdx.x & 31;
    int g     = lane >> 2;
    int lane4 = lane & 3;
    const char* xsb = xs + lane4 * 16;

    int bid = blockIdx.x;
    int c, b0, bstep;
    if (bid < NFULL) { c = bid; b0 = w; bstep = 32; }
    else {
        int t = bid - NFULL;
        c = NFULL + (t >> 2);
        int qi = t & 3;
        b0 = qi + (w << 2);
        bstep = 128;
    }

    // copy fp16 tile [n_slots][32] -> smem at stride SSTRIDE
    {
        const uint4* src = (const uint4*)(getact(asel) + (size_t)c * n_slots * 32);
        int nq = n_slots * 4;
        for (int t = threadIdx.x; t < nq; t += 1024) {
            int slot = t >> 2, q = t & 3;
            *(uint4*)(xs + slot * SSTRIDE + q * 16) = src[t];
        }
    }
    __syncthreads();

    float* yb = g_Y + (size_t)c * S32;
    for (int b = b0; b < NB; b += bstep) {
        int pp = b * 8 + g;
        int j  = g_perm[layer * NBP8 + pp];
        int km = g_blkmax[layer * NB + b];
        int kmp = (km + 1) >> 1;
        const int4* ep4 = g_be2 + (size_t)(layer * NB + b) * CAPP * 8 + g;
        unsigned long long acc0 = 0, acc1 = 0, acc2 = 0, acc3 = 0; // f32x2 {0,0}
        if (kmp > 0) {
            int4 e = ep4[0];
            for (int kp = 0; kp < kmp; kp++) {
                int4 en;
                if (kp + 1 < kmp) en = ep4[(size_t)(kp + 1) * 8];
                uint4 r0 = *(const uint4*)(xsb + e.x);
                uint4 r1 = *(const uint4*)(xsb + e.z);
                unsigned long long w0p = f_dup(__int_as_float(e.y));
                unsigned long long w1p = f_dup(__int_as_float(e.w));
                ffma2(acc0, h2_up(r0.x), w0p);
                ffma2(acc1, h2_up(r0.y), w0p);
                ffma2(acc2, h2_up(r0.z), w0p);
                ffma2(acc3, h2_up(r0.w), w0p);
                ffma2(acc0, h2_up(r1.x), w1p);
                ffma2(acc1, h2_up(r1.y), w1p);
                ffma2(acc2, h2_up(r1.z), w1p);
                ffma2(acc3, h2_up(r1.w), w1p);
                e = en;
            }
        }
        float2 f0 = unpk(acc0), f1 = unpk(acc1), f2 = unpk(acc2), f3 = unpk(acc3);
        // BN partials: shuffles MUST run convergent (pad lanes j==-1 included).
        float s  = f0.x + f0.y + f1.x + f1.y + f2.x + f2.y + f3.x + f3.y;
        float ss = f0.x * f0.x + f0.y * f0.y + f1.x * f1.x + f1.y * f1.y
                 + f2.x * f2.x + f2.y * f2.y + f3.x * f3.x + f3.y * f3.y;
        s  += __shfl_xor_sync(0xffffffffu, s, 1);
        ss += __shfl_xor_sync(0xffffffffu, ss, 1);
        s  += __shfl_xor_sync(0xffffffffu, s, 2);
        ss += __shfl_xor_sync(0xffffffffu, ss, 2);
        if (j >= 0) {
            float4* dst = (float4*)(yb + (size_t)j * 32 + lane4 * 8);
            dst[0] = make_float4(f0.x, f0.y, f1.x, f1.y);
            dst[1] = make_float4(f2.x, f2.y, f3.x, f3.y);
            if (lane4 == 0)
                g_part[(size_t)j * NCH + c] = make_float2(s, ss);
        }
    }
}

// ---------------- stats: fold partials + gamma/beta/diag into float4 ---------
__global__ __launch_bounds__(256)
void stats_kernel(const float* __restrict__ gamma, const float* __restrict__ beta,
                  const float* __restrict__ dvec) {
    int j = blockIdx.x * 8 + (threadIdx.x >> 5);
    if (j >= S) return;
    int ln = threadIdx.x & 31;
    const float2* pt = g_part + (size_t)j * NCH;
    float s = 0.f, ss = 0.f;
    #pragma unroll
    for (int i = 0; i < 8; i++) {
        float2 v = pt[ln + 32 * i];
        s += v.x; ss += v.y;
    }
    #pragma unroll
    for (int o = 16; o; o >>= 1) {
        s  += __shfl_xor_sync(0xffffffffu, s,  o);
        ss += __shfl_xor_sync(0xffffffffu, ss, o);
    }
    if (ln == 0) {
        float m   = s * (1.f / 8192.f);
        float var = ss * (1.f / 8192.f) - m * m;
        float rstd = rsqrtf(var + 1e-5f);
        g_stat[j] = make_float4(m, gamma[j] * rstd, beta[j],
                                dvec ? dvec[j] : 0.f);
    }
}

// ---------------- output head: applies layer-6 BN/tanh/skip inline -----------
__global__ __launch_bounds__(512)
void out_kernel(int ssel, const float* __restrict__ fasm,
                const float* __restrict__ wout, const float* __restrict__ bout,
                float* __restrict__ out) {
    __shared__ float fw[S];
    for (int i = threadIdx.x; i < S; i += blockDim.x) fw[i] = fasm[i] * wout[i];
    __syncthreads();
    int b = blockIdx.x * blockDim.x + threadIdx.x;
    int c = b >> 5, lane = b & 31;
    const float*  Yb = g_Y + (size_t)c * S32 + lane;
    const __half* sb = getact(ssel) + (size_t)c * S32 + lane;
    float s = *bout;
    for (int jj = 0; jj < S; jj++) {
        float f = fw[jj];
        if (f != 0.f) {
            float4 st = g_stat[jj];
            float y  = Yb[(size_t)jj * 32];
            float a5 = __half2float(sb[(size_t)jj * 32]);
            float a6 = tanhf((y - st.x) * st.y + st.z) + a5 * st.w;
            s += a6 * f;
        }
    }
    out[b] = s;
}

// ---------------- launch ------------------------------------------------------
extern "C" void kernel_launch(void* const* d_in, const int* in_sizes, int n_in,
                              void* d_out, int out_size) {
    const float* x     = (const float*)d_in[0];
    const float* lm0   = (const float*)d_in[1];
    const float* lm    = (const float*)d_in[2];
    const float* flm   = (const float*)d_in[3];
    const float* fasm  = (const float*)d_in[4];
    const float* W0    = (const float*)d_in[5];
    const float* W     = (const float*)d_in[7];
    const float* gamma = (const float*)d_in[9];
    const float* beta  = (const float*)d_in[10];
    const float* wout  = (const float*)d_in[11];
    const float* bout  = (const float*)d_in[12];
    float* out = (float*)d_out;
    // note: biases b0/b (d_in[6], d_in[8]) cancel exactly through training-mode BN

    cudaFuncSetAttribute(spmm_kernel, cudaFuncAttributeMaxDynamicSharedMemorySize,
                         S * SSTRIDE);

    // 1) build sparse structure
    bits_kernel<<<dim3((S + 127) / 128, NLAY, NW), 128>>>(lm0, lm);
    prefix_kernel<<<dim3((S + 127) / 128, NLAY), 128>>>();
    sort_kernel<<<dim3((S + 1023) / 1024, NLAY), 1024>>>();
    fill_kernel<<<dim3((NBP8 + 127) / 128, NLAY, RSPLIT), 128>>>(W0, W);

    // 2) transpose x -> actA (fp16, 32-wide chunks)
    xt_kernel<<<dim3((G + XT_TI - 1) / XT_TI, NCH), 256>>>(x);

    // 3) layer 0: gather x (actA) -> Y0 + partials; stats0
    spmm_kernel<<<NGRID, 1024, G * SSTRIDE>>>(0, 0, G);
    stats_kernel<<<(S + 7) / 8, 256>>>(gamma, beta, nullptr);

    // 4) layers 1..6: t_kernel (once per chunk, balanced) then gather + stats
    for (int l = 1; l <= 6; l++) {
        int wsel = (l & 1) ? 1 : 0;   // h_{l-1} buffer
        int ssel = 1 - wsel;          // h_{l-2} (or x-fp16 for l=1, d=0)
        t_kernel<<<dim3(TQ, NCH), 512>>>(wsel, ssel);
        spmm_kernel<<<NGRID, 1024, S * SSTRIDE>>>(wsel, l, S);
        stats_kernel<<<(S + 7) / 8, 256>>>(gamma + (size_t)l * S,
                                           beta + (size_t)l * S,
                                           flm + (size_t)(l - 1) * S);
    }

    // 5) output head (layer-6 activation computed inline; h_5 is in actA)
    out_kernel<<<16, 512>>>(0, fasm, wout, bout, out);
}

// round 16
// speedup vs baseline: 1.0857x; 1.0164x over previous
#include <cuda_runtime.h>
#include <cuda_fp16.h>

// Problem constants
#define S      2785
#define S32    (S * 32)
#define G      689
#define NCH    256            // batch chunks of 32
#define CAP    192            // max nnz per column
#define CAPP   (CAP / 2)      // entry pairs
#define NLAY   7
#define RSPLIT 8
#define NW     88             // bitmap words per column
#define WPC    11
#define NB     349            // column blocks of 8
#define NBP8   (NB * 8)
#define NFULL  148            // full-chunk CTAs (chunks 0..147)
#define NTAIL  (NCH - NFULL)  // 108 tail chunks
#define NQRT   (NTAIL * 4)    // 432 quarter-chunk CTAs
#define NGRID  (NFULL + NQRT) // 580
#define SSTRIDE 80            // smem bytes per slot (32 halfs + 16B pad)

// ---------------- device global scratch ---------------------------------------
__device__ __half    g_actA[(size_t)NCH * S32];
__device__ __half    g_actB[(size_t)NCH * S32];
__device__ float     g_Y[(size_t)NCH * S32];
__device__ int4      g_be2[(size_t)NLAY * NB * CAPP * 8];
__device__ float2    g_part[(size_t)S * NCH];
__device__ float4    g_stat[S];                  // {mean, gamma*rstd, beta, d}
__device__ unsigned  g_bits[(size_t)NLAY * NW * S];
__device__ int       g_cnt[NLAY * S];
__device__ int       g_off8[NLAY * RSPLIT * S];
__device__ int       g_perm[NLAY * NBP8];
__device__ int       g_scnt[NLAY * NBP8];
__device__ int       g_blkmax[NLAY * NB];

__device__ __forceinline__ __half* getact(int s) { return s == 0 ? g_actA : g_actB; }

// packed f32x2 helpers (Blackwell FFMA2 path)
__device__ __forceinline__ unsigned long long h2_up(unsigned h2) {
    float2 f = __half22float2(*(__half2*)&h2);
    unsigned long long r;
    asm("mov.b64 %0, {%1, %2};" : "=l"(r) : "f"(f.x), "f"(f.y));
    return r;
}
__device__ __forceinline__ unsigned long long f_dup(float w) {
    unsigned long long r;
    asm("mov.b64 %0, {%1, %1};" : "=l"(r) : "f"(w));
    return r;
}
__device__ __forceinline__ void ffma2(unsigned long long& acc,
                                      unsigned long long a, unsigned long long b) {
    asm("fma.rn.f32x2 %0, %1, %2, %0;" : "+l"(acc) : "l"(a), "l"(b));
}
__device__ __forceinline__ float2 unpk(unsigned long long v) {
    float2 f;
    asm("mov.b64 {%0, %1}, %2;" : "=f"(f.x), "=f"(f.y) : "l"(v));
    return f;
}

// shared transform step: 8 lanes of one slot
__device__ __forceinline__ uint2 bn_tanh_skip(float4 st, float4 y, uint2 sk) {
    float2 s0 = __half22float2(*(__half2*)&sk.x);
    float2 s1 = __half22float2(*(__half2*)&sk.y);
    float a0 = tanhf((y.x - st.x) * st.y + st.z) + s0.x * st.w;
    float a1 = tanhf((y.y - st.x) * st.y + st.z) + s0.y * st.w;
    float a2 = tanhf((y.z - st.x) * st.y + st.z) + s1.x * st.w;
    float a3 = tanhf((y.w - st.x) * st.y + st.z) + s1.y * st.w;
    __half2 h0 = __floats2half2_rn(a0, a1);
    __half2 h1 = __floats2half2_rn(a2, a3);
    uint2 pk;
    *(__half2*)&pk.x = h0;
    *(__half2*)&pk.y = h1;
    return pk;
}

// ---------------- build phase A: occupancy bitmaps ----------------------------
__global__ void bits_kernel(const float* __restrict__ lm0, const float* __restrict__ lm) {
    int l = blockIdx.y;
    int w = blockIdx.z;
    int j = blockIdx.x * 128 + threadIdx.x;
    if (j >= S) return;
    int rows = (l == 0) ? G : S;
    unsigned m = 0;
    int i0 = w * 32;
    if (i0 < rows) {
        const float* M = (l == 0) ? lm0 : lm + (size_t)(l - 1) * S * S;
        const float* Mr = M + (size_t)i0 * S + j;
        if (i0 + 32 <= rows) {
            #pragma unroll
            for (int k = 0; k < 32; k++)
                m |= (Mr[(size_t)k * S] != 0.f ? 1u : 0u) << k;
        } else {
            int n = rows - i0;
            for (int k = 0; k < n; k++)
                m |= (Mr[(size_t)k * S] != 0.f ? 1u : 0u) << k;
        }
    }
    g_bits[((size_t)l * NW + w) * S + j] = m;
}

// ---------------- build phase B: per-chunk popc prefix ------------------------
__global__ void prefix_kernel() {
    int l = blockIdx.y;
    int j = blockIdx.x * 128 + threadIdx.x;
    if (j >= S) return;
    int off = 0;
    #pragma unroll
    for (int r = 0; r < RSPLIT; r++) {
        int c = 0;
        #pragma unroll
        for (int w = r * WPC; w < (r + 1) * WPC; w++)
            c += __popc(g_bits[((size_t)l * NW + w) * S + j]);
        g_off8[(l * RSPLIT + r) * S + j] = off;
        off += c;
    }
    g_cnt[l * S + j] = min(off, CAP);
}

// ---------------- build phase C: deterministic rank-sort ----------------------
#define S4 ((S + 3) / 4)
__global__ __launch_bounds__(1024)
void sort_kernel() {
    int l = blockIdx.y;
    __shared__ int4 scnt4[S4];
    int* scnt = (int*)scnt4;
    for (int j = threadIdx.x; j < S4 * 4; j += 1024)
        scnt[j] = (j < S) ? g_cnt[l * S + j] : -1;
    __syncthreads();

    int j = blockIdx.x * 1024 + threadIdx.x;
    if (j < S) {
        int c = scnt[j];
        int pos = 0;
        for (int q = 0; q < S4; q++) {
            int4 v = scnt4[q];
            int b0 = 4 * q;
            pos += (v.x > c) || (v.x == c && b0 + 0 < j);
            pos += (v.y > c) || (v.y == c && b0 + 1 < j);
            pos += (v.z > c) || (v.z == c && b0 + 2 < j);
            pos += (v.w > c) || (v.w == c && b0 + 3 < j);
        }
        g_perm[l * NBP8 + pos] = j;
        g_scnt[l * NBP8 + pos] = c;
        if ((pos & 7) == 0) g_blkmax[l * NB + (pos >> 3)] = c;
    }
    if (blockIdx.x == 0)
        for (int p = S + threadIdx.x; p < NBP8; p += 1024) {
            g_perm[l * NBP8 + p] = -1;
            g_scnt[l * NBP8 + p] = 0;
        }
}

// ---------------- build phase D: fill entries from bitmaps + zero-pad --------
__global__ void fill_kernel(const float* __restrict__ W0, const float* __restrict__ Wl) {
    int l = blockIdx.y, r = blockIdx.z;
    int p = blockIdx.x * 128 + threadIdx.x;
    if (p >= NBP8) return;
    int j = g_perm[l * NBP8 + p];
    int b = p >> 3, g = p & 7;
    int2* e2 = (int2*)g_be2;
    size_t bi = (size_t)(l * NB + b) * CAPP;
    int km = g_blkmax[l * NB + b];
    int kmpad = ((km + 1) >> 1) << 1;

    if (j < 0) {
        if (r == RSPLIT - 1)
            for (int k = 0; k < kmpad; k++)
                e2[((bi + (k >> 1)) * 8 + g) * 2 + (k & 1)] = make_int2(0, 0);
        return;
    }
    const float* Wm = (l == 0) ? W0 : Wl + (size_t)(l - 1) * S * S;
    int o = g_off8[(l * RSPLIT + r) * S + j];
    for (int w = r * WPC; w < (r + 1) * WPC; w++) {
        unsigned m = g_bits[((size_t)l * NW + w) * S + j];
        int ibase = w * 32;
        while (m) {
            int k = __ffs(m) - 1;
            m &= m - 1;
            int i = ibase + k;
            if (o < CAP) {
                float wv = Wm[(size_t)i * S + j];
                e2[((bi + (o >> 1)) * 8 + g) * 2 + (o & 1)] =
                    make_int2(i * SSTRIDE, __float_as_int(wv));
            }
            o++;
        }
    }
    if (r == RSPLIT - 1) {
        int start = g_scnt[l * NBP8 + p];
        for (int k = start; k < kmpad; k++)
            e2[((bi + (k >> 1)) * 8 + g) * 2 + (k & 1)] = make_int2(0, 0);
    }
}

// ---------------- coalesced transpose x [B,G] -> [NCH][G][32] fp16 -----------
#define XT_TI 128
__global__ __launch_bounds__(256)
void xt_kernel(const float* __restrict__ x) {
    __shared__ float tile[32][XT_TI + 1];
    int c  = blockIdx.y;
    int i0 = blockIdx.x * XT_TI;
    int t  = threadIdx.x;
    int col = t & 127;
    #pragma unroll
    for (int rr = 0; rr < 16; rr++) {
        int row = rr * 2 + (t >> 7);
        int i = i0 + col;
        tile[row][col] = (i < G) ? x[(size_t)(c * 32 + row) * G + i] : 0.f;
    }
    __syncthreads();
    int lane = t & 31;
    int ii0 = t >> 5;
    #pragma unroll
    for (int bq = 0; bq < 16; bq++) {
        int ii = ii0 + bq * 8;
        int i = i0 + ii;
        if (i < G)
            g_actA[(size_t)c * (G * 32) + (size_t)i * 32 + lane] =
                __float2half_rn(tile[lane][ii]);
    }
}

// ---------------- t_kernel: transform TAIL chunks only (148..255) -------------
#define TQ ((S * 8 + 511) / 512)
__global__ __launch_bounds__(512)
void t_kernel(int wsel, int ssel) {
    int c = NFULL + blockIdx.y;
    int q = blockIdx.x * 512 + threadIdx.x;
    if (q >= S * 8) return;
    int slot = q >> 3, oct = q & 7;
    float4 st = g_stat[slot];
    float4 y  = *(const float4*)(g_Y + (size_t)c * S32 + slot * 32 + oct * 4);
    uint2 sk  = *(const uint2*)(getact(ssel) + (size_t)c * S32 + slot * 32 + oct * 4);
    uint2 pk = bn_tanh_skip(st, y, sk);
    *(uint2*)(getact(wsel) + (size_t)c * S32 + slot * 32 + oct * 4) = pk;
}

// ---------------- SpMM: tile load (copy or fused transform) + gather + stats --
// mode 0: all CTAs copy act tile from getact(wsel) (layer 0)
// mode 1: full CTAs fuse transform (Y+skip -> smem + act write, once per chunk);
//         quarter CTAs copy act written by t_kernel
__global__ __launch_bounds__(1024, 1)
void spmm_kernel(int mode, int wsel, int ssel, int layer, int n_slots) {
    extern __shared__ char xs[];

    int w     = threadIdx.x >> 5;
    int lane  = threadIdx.x & 31;
    int g     = lane >> 2;
    int lane4 = lane & 3;
    const char* xsb = xs + lane4 * 16;

    int bid = blockIdx.x;
    int c, b0, bstep, isfull;
    if (bid < NFULL) { c = bid; b0 = w; bstep = 32; isfull = 1; }
    else {
        int t = bid - NFULL;
        c = NFULL + (t >> 2);
        int qi = t & 3;
        b0 = qi + (w << 2);
        bstep = 128;
        isfull = 0;
    }

    if (mode == 1 && isfull) {
        // fused transform: read Y + skip, write act (once) + smem tile
        const float* Yc = g_Y + (size_t)c * S32;
        const __half* skp = getact(ssel) + (size_t)c * S32;
        __half* actw = getact(wsel) + (size_t)c * S32;
        for (int q = threadIdx.x; q < S * 8; q += 1024) {
            int slot = q >> 3, oct = q & 7;
            float4 st = g_stat[slot];
            float4 y  = *(const float4*)(Yc + slot * 32 + oct * 4);
            uint2 sk  = *(const uint2*)(skp + slot * 32 + oct * 4);
            uint2 pk = bn_tanh_skip(st, y, sk);
            *(uint2*)(xs + slot * SSTRIDE + oct * 8) = pk;
            *(uint2*)(actw + slot * 32 + oct * 4) = pk;
        }
    } else {
        // plain copy of fp16 act tile
        const uint4* src = (const uint4*)(getact(wsel) + (size_t)c * n_slots * 32);
        int nq = n_slots * 4;
        for (int t = threadIdx.x; t < nq; t += 1024) {
            int slot = t >> 2, q = t & 3;
            *(uint4*)(xs + slot * SSTRIDE + q * 16) = src[t];
        }
    }
    __syncthreads();

    float* yb = g_Y + (size_t)c * S32;
    for (int b = b0; b < NB; b += bstep) {
        int pp = b * 8 + g;
        int j  = g_perm[layer * NBP8 + pp];
        int km = g_blkmax[layer * NB + b];
        int kmp = (km + 1) >> 1;
        const int4* ep4 = g_be2 + (size_t)(layer * NB + b) * CAPP * 8 + g;
        unsigned long long acc0 = 0, acc1 = 0, acc2 = 0, acc3 = 0; // f32x2 {0,0}
        if (kmp > 0) {
            int4 e = ep4[0];
            for (int kp = 0; kp < kmp; kp++) {
                int4 en;
                if (kp + 1 < kmp) en = ep4[(size_t)(kp + 1) * 8];
                uint4 r0 = *(const uint4*)(xsb + e.x);
                uint4 r1 = *(const uint4*)(xsb + e.z);
                unsigned long long w0p = f_dup(__int_as_float(e.y));
                unsigned long long w1p = f_dup(__int_as_float(e.w));
                ffma2(acc0, h2_up(r0.x), w0p);
                ffma2(acc1, h2_up(r0.y), w0p);
                ffma2(acc2, h2_up(r0.z), w0p);
                ffma2(acc3, h2_up(r0.w), w0p);
                ffma2(acc0, h2_up(r1.x), w1p);
                ffma2(acc1, h2_up(r1.y), w1p);
                ffma2(acc2, h2_up(r1.z), w1p);
                ffma2(acc3, h2_up(r1.w), w1p);
                e = en;
            }
        }
        float2 f0 = unpk(acc0), f1 = unpk(acc1), f2 = unpk(acc2), f3 = unpk(acc3);
        // BN partials: shuffles MUST run convergent (pad lanes j==-1 included).
        float s  = f0.x + f0.y + f1.x + f1.y + f2.x + f2.y + f3.x + f3.y;
        float ss = f0.x * f0.x + f0.y * f0.y + f1.x * f1.x + f1.y * f1.y
                 + f2.x * f2.x + f2.y * f2.y + f3.x * f3.x + f3.y * f3.y;
        s  += __shfl_xor_sync(0xffffffffu, s, 1);
        ss += __shfl_xor_sync(0xffffffffu, ss, 1);
        s  += __shfl_xor_sync(0xffffffffu, s, 2);
        ss += __shfl_xor_sync(0xffffffffu, ss, 2);
        if (j >= 0) {
            float4* dst = (float4*)(yb + (size_t)j * 32 + lane4 * 8);
            dst[0] = make_float4(f0.x, f0.y, f1.x, f1.y);
            dst[1] = make_float4(f2.x, f2.y, f3.x, f3.y);
            if (lane4 == 0)
                g_part[(size_t)j * NCH + c] = make_float2(s, ss);
        }
    }
}

// ---------------- stats: fold partials + gamma/beta/diag into float4 ---------
__global__ __launch_bounds__(256)
void stats_kernel(const float* __restrict__ gamma, const float* __restrict__ beta,
                  const float* __restrict__ dvec) {
    int j = blockIdx.x * 8 + (threadIdx.x >> 5);
    if (j >= S) return;
    int ln = threadIdx.x & 31;
    const float2* pt = g_part + (size_t)j * NCH;
    float s = 0.f, ss = 0.f;
    #pragma unroll
    for (int i = 0; i < 8; i++) {
        float2 v = pt[ln + 32 * i];
        s += v.x; ss += v.y;
    }
    #pragma unroll
    for (int o = 16; o; o >>= 1) {
        s  += __shfl_xor_sync(0xffffffffu, s,  o);
        ss += __shfl_xor_sync(0xffffffffu, ss, o);
    }
    if (ln == 0) {
        float m   = s * (1.f / 8192.f);
        float var = ss * (1.f / 8192.f) - m * m;
        float rstd = rsqrtf(var + 1e-5f);
        g_stat[j] = make_float4(m, gamma[j] * rstd, beta[j],
                                dvec ? dvec[j] : 0.f);
    }
}

// ---------------- output head: applies layer-6 BN/tanh/skip inline -----------
__global__ __launch_bounds__(512)
void out_kernel(int ssel, const float* __restrict__ fasm,
                const float* __restrict__ wout, const float* __restrict__ bout,
                float* __restrict__ out) {
    __shared__ float fw[S];
    for (int i = threadIdx.x; i < S; i += blockDim.x) fw[i] = fasm[i] * wout[i];
    __syncthreads();
    int b = blockIdx.x * blockDim.x + threadIdx.x;
    int c = b >> 5, lane = b & 31;
    const float*  Yb = g_Y + (size_t)c * S32 + lane;
    const __half* sb = getact(ssel) + (size_t)c * S32 + lane;
    float s = *bout;
    for (int jj = 0; jj < S; jj++) {
        float f = fw[jj];
        if (f != 0.f) {
            float4 st = g_stat[jj];
            float y  = Yb[(size_t)jj * 32];
            float a5 = __half2float(sb[(size_t)jj * 32]);
            float a6 = tanhf((y - st.x) * st.y + st.z) + a5 * st.w;
            s += a6 * f;
        }
    }
    out[b] = s;
}

// ---------------- launch ------------------------------------------------------
extern "C" void kernel_launch(void* const* d_in, const int* in_sizes, int n_in,
                              void* d_out, int out_size) {
    const float* x     = (const float*)d_in[0];
    const float* lm0   = (const float*)d_in[1];
    const float* lm    = (const float*)d_in[2];
    const float* flm   = (const float*)d_in[3];
    const float* fasm  = (const float*)d_in[4];
    const float* W0    = (const float*)d_in[5];
    const float* W     = (const float*)d_in[7];
    const float* gamma = (const float*)d_in[9];
    const float* beta  = (const float*)d_in[10];
    const float* wout  = (const float*)d_in[11];
    const float* bout  = (const float*)d_in[12];
    float* out = (float*)d_out;
    // note: biases b0/b (d_in[6], d_in[8]) cancel exactly through training-mode BN

    cudaFuncSetAttribute(spmm_kernel, cudaFuncAttributeMaxDynamicSharedMemorySize,
                         S * SSTRIDE);

    // 1) build sparse structure
    bits_kernel<<<dim3((S + 127) / 128, NLAY, NW), 128>>>(lm0, lm);
    prefix_kernel<<<dim3((S + 127) / 128, NLAY), 128>>>();
    sort_kernel<<<dim3((S + 1023) / 1024, NLAY), 1024>>>();
    fill_kernel<<<dim3((NBP8 + 127) / 128, NLAY, RSPLIT), 128>>>(W0, W);

    // 2) transpose x -> actA (fp16, 32-wide chunks)
    xt_kernel<<<dim3((G + XT_TI - 1) / XT_TI, NCH), 256>>>(x);

    // 3) layer 0: gather x (actA) -> Y0 + partials; stats0
    spmm_kernel<<<NGRID, 1024, G * SSTRIDE>>>(0, 0, 0, 0, G);
    stats_kernel<<<(S + 7) / 8, 256>>>(gamma, beta, nullptr);

    // 4) layers 1..6: t_kernel for TAIL chunks, fused transform in full CTAs
    for (int l = 1; l <= 6; l++) {
        int wsel = (l & 1) ? 1 : 0;   // h_{l-1} buffer
        int ssel = 1 - wsel;          // h_{l-2} (x-fp16 for l=1; d=0 kills it)
        t_kernel<<<dim3(TQ, NTAIL), 512>>>(wsel, ssel);
        spmm_kernel<<<NGRID, 1024, S * SSTRIDE>>>(1, wsel, ssel, l, S);
        stats_kernel<<<(S + 7) / 8, 256>>>(gamma + (size_t)l * S,
                                           beta + (size_t)l * S,
                                           flm + (size_t)(l - 1) * S);
    }

    // 5) output head (layer-6 activation computed inline; h_5 is in actA)
    out_kernel<<<16, 512>>>(0, fasm, wout, bout, out);
}